// round 1
// baseline (speedup 1.0000x reference)
#include <cuda_runtime.h>
#include <cstdint>

// Problem constants (fixed by the dataset generator)
#define NN      50000
#define NMSG    200

// ---------------------------------------------------------------------------
// Static device scratch (allocation-free rule: __device__ globals only)
// ---------------------------------------------------------------------------
__device__ __align__(16) float g_x0[NN * 30];
__device__ __align__(16) float g_x1[NN * 30];
__device__ __align__(16) float g_A [NN * NMSG];   // per-node dst-side precompute (+bm1)
__device__ __align__(16) float g_B [NN * NMSG];   // per-node src-side precompute
__device__ int g_is64;

// ---------------------------------------------------------------------------
// Edge index dtype detection: reference says int64, but JAX w/o x64 gives
// int32. If the first 16 values interpreted as int64 are all in [0, NN),
// it is int64 (int32-pair aliasing would almost surely produce a huge value).
// ---------------------------------------------------------------------------
__global__ void detect_edges_kernel(const long long* __restrict__ e64) {
    if (threadIdx.x == 0 && blockIdx.x == 0) {
        int ok = 1;
        for (int i = 0; i < 16; i++) {
            long long v = e64[i];
            if (v < 0 || v >= NN) ok = 0;
        }
        g_is64 = ok;
    }
}

// ---------------------------------------------------------------------------
// Per-node precompute: A[n,k] = sum_c x[n,c]*Wm1[c,k] + bm1[k]
//                      B[n,k] = sum_c x[n,c]*Wm1[C_IN+c,k]
// (folds the linear part of mlp[0] acting on xi / xj into node space)
// ---------------------------------------------------------------------------
template <int C_IN>
__global__ void precomp_ab_kernel(const float* __restrict__ x,
                                  const float* __restrict__ Wm1,
                                  const float* __restrict__ bm1,
                                  float* __restrict__ A,
                                  float* __restrict__ B,
                                  int N) {
    int idx = blockIdx.x * blockDim.x + threadIdx.x;
    if (idx >= N * NMSG) return;
    int n = idx / NMSG;
    int k = idx - n * NMSG;
    float a = bm1[k];
    float b = 0.f;
#pragma unroll
    for (int c = 0; c < C_IN; c++) {
        float xv = x[(size_t)n * C_IN + c];
        a = fmaf(xv, Wm1[c * NMSG + k], a);
        b = fmaf(xv, Wm1[(C_IN + c) * NMSG + k], b);
    }
    A[idx] = a;
    B[idx] = b;
}

// ---------------------------------------------------------------------------
// Node self-term: out[n,co] = b1[co] + sum_c x[n,c] * W1[c,co]
// Also serves as the initializer of the aggregation buffer.
// ---------------------------------------------------------------------------
template <int C_IN, int C_OUT>
__global__ void node_init_kernel(const float* __restrict__ x,
                                 const float* __restrict__ W1,
                                 const float* __restrict__ b1,
                                 float* __restrict__ out,
                                 int N) {
    int idx = blockIdx.x * blockDim.x + threadIdx.x;
    if (idx >= N * C_OUT) return;
    int n  = idx / C_OUT;
    int co = idx - n * C_OUT;
    float v = b1[co];
#pragma unroll
    for (int c = 0; c < C_IN; c++)
        v = fmaf(x[(size_t)n * C_IN + c], W1[c * C_OUT + co], v);
    out[idx] = v;
}

__global__ void relu_kernel(float* __restrict__ x, int n) {
    int idx = blockIdx.x * blockDim.x + threadIdx.x;
    if (idx < n) x[idx] = fmaxf(x[idx], 0.f);
}

// ---------------------------------------------------------------------------
// Edge kernel: one thread per edge.
//   h_k  = relu( A[dst,k] + B[src,k] + ea0*Wm1[2C,k] + ea1*Wm1[2C+1,k] )
//   m_c  = sum_k h_k * Wm2[k,c]  + bm2[c]
//   t_c  = m_c * (x[dst,c] - x[src,c])
//   msg  = t @ W2 + b2   -> atomicAdd into out[dst]
// Weights staged in shared (float4, padded rows for 16B-aligned broadcasts).
// ---------------------------------------------------------------------------
template <int C_IN, int C_OUT>
__global__ void __launch_bounds__(256)
edge_kernel(const void* __restrict__ edges,
            const float* __restrict__ ea,
            const float* __restrict__ x,
            const float* __restrict__ A,
            const float* __restrict__ B,
            const float* __restrict__ Wm1,
            const float* __restrict__ Wm2,
            const float* __restrict__ bm2,
            const float* __restrict__ W2,
            const float* __restrict__ b2,
            float* __restrict__ out,
            int E) {
    constexpr int C4  = (C_IN + 3) / 4;
    constexpr int CIP = C4 * 4;          // padded input channels (32 / 4)
    constexpr int CO4 = (C_OUT + 3) / 4;
    constexpr int COP = CO4 * 4;         // padded output channels (32 / 4)

    __shared__ __align__(16) float sWE[2 * NMSG];        // edge-attr rows of Wm1
    __shared__ __align__(16) float sWm2[NMSG * CIP];     // [k][c] padded
    __shared__ __align__(16) float sW2[C_IN * COP];      // [c][co] padded
    __shared__ float sbm2[C_IN];
    __shared__ __align__(16) float sb2[COP];

    const int tid = threadIdx.x;
    for (int i = tid; i < 2 * NMSG; i += 256) sWE[i] = Wm1[2 * C_IN * NMSG + i];
    for (int i = tid; i < NMSG * CIP; i += 256) {
        int k = i / CIP, c = i - k * CIP;
        sWm2[i] = (c < C_IN) ? Wm2[k * C_IN + c] : 0.f;
    }
    for (int i = tid; i < C_IN * COP; i += 256) {
        int c = i / COP, co = i - c * COP;
        sW2[i] = (co < C_OUT) ? W2[c * C_OUT + co] : 0.f;
    }
    for (int i = tid; i < C_IN; i += 256) sbm2[i] = bm2[i];
    for (int i = tid; i < COP; i += 256) sb2[i] = (i < C_OUT) ? b2[i] : 0.f;
    __syncthreads();

    int e = blockIdx.x * 256 + tid;
    if (e >= E) return;

    int src, dst;
    if (g_is64) {
        const long long* p = (const long long*)edges;
        src = (int)p[e];
        dst = (int)p[(size_t)E + e];
    } else {
        const int* p = (const int*)edges;
        src = p[e];
        dst = p[E + e];
    }

    float2 w = ((const float2*)ea)[e];

    // xi - xj (only the difference is needed downstream)
    float dreg[C_IN];
#pragma unroll
    for (int c = 0; c < C_IN; c++)
        dreg[c] = x[(size_t)dst * C_IN + c] - x[(size_t)src * C_IN + c];

    const float4* A4  = (const float4*)(A + (size_t)dst * NMSG);
    const float4* B4  = (const float4*)(B + (size_t)src * NMSG);
    const float4* WE0 = (const float4*)(sWE);
    const float4* WE1 = (const float4*)(sWE + NMSG);

    float4 macc[C4];
#pragma unroll
    for (int j = 0; j < C4; j++) macc[j] = make_float4(0.f, 0.f, 0.f, 0.f);

#pragma unroll 2
    for (int kg = 0; kg < NMSG / 4; kg++) {
        float4 a = A4[kg];
        float4 b = B4[kg];
        float4 u0 = WE0[kg];
        float4 u1 = WE1[kg];
        float hx = fmaxf(fmaf(w.x, u0.x, fmaf(w.y, u1.x, a.x + b.x)), 0.f);
        float hy = fmaxf(fmaf(w.x, u0.y, fmaf(w.y, u1.y, a.y + b.y)), 0.f);
        float hz = fmaxf(fmaf(w.x, u0.z, fmaf(w.y, u1.z, a.z + b.z)), 0.f);
        float hw = fmaxf(fmaf(w.x, u0.w, fmaf(w.y, u1.w, a.w + b.w)), 0.f);

        const float4* r0 = (const float4*)(sWm2 + (4 * kg + 0) * CIP);
        const float4* r1 = (const float4*)(sWm2 + (4 * kg + 1) * CIP);
        const float4* r2 = (const float4*)(sWm2 + (4 * kg + 2) * CIP);
        const float4* r3 = (const float4*)(sWm2 + (4 * kg + 3) * CIP);
#pragma unroll
        for (int j = 0; j < C4; j++) {
            float4 q0 = r0[j], q1 = r1[j], q2 = r2[j], q3 = r3[j];
            macc[j].x = fmaf(hx, q0.x, fmaf(hy, q1.x, fmaf(hz, q2.x, fmaf(hw, q3.x, macc[j].x))));
            macc[j].y = fmaf(hx, q0.y, fmaf(hy, q1.y, fmaf(hz, q2.y, fmaf(hw, q3.y, macc[j].y))));
            macc[j].z = fmaf(hx, q0.z, fmaf(hy, q1.z, fmaf(hz, q2.z, fmaf(hw, q3.z, macc[j].z))));
            macc[j].w = fmaf(hx, q0.w, fmaf(hy, q1.w, fmaf(hz, q2.w, fmaf(hw, q3.w, macc[j].w))));
        }
    }

    // t_c = (m_c + bm2_c) * (xi - xj)_c, stored back into dreg
#pragma unroll
    for (int j = 0; j < C4; j++) {
        int c = 4 * j;
        if (c + 0 < C_IN) dreg[c + 0] = (macc[j].x + sbm2[c + 0]) * dreg[c + 0];
        if (c + 1 < C_IN) dreg[c + 1] = (macc[j].y + sbm2[c + 1]) * dreg[c + 1];
        if (c + 2 < C_IN) dreg[c + 2] = (macc[j].z + sbm2[c + 2]) * dreg[c + 2];
        if (c + 3 < C_IN) dreg[c + 3] = (macc[j].w + sbm2[c + 3]) * dreg[c + 3];
    }

    // msg = t @ W2 + b2
    float4 vacc[CO4];
    const float4* sb24 = (const float4*)sb2;
#pragma unroll
    for (int j = 0; j < CO4; j++) vacc[j] = sb24[j];
#pragma unroll
    for (int c = 0; c < C_IN; c++) {
        float tv = dreg[c];
        const float4* wr = (const float4*)(sW2 + c * COP);
#pragma unroll
        for (int j = 0; j < CO4; j++) {
            float4 q = wr[j];
            vacc[j].x = fmaf(tv, q.x, vacc[j].x);
            vacc[j].y = fmaf(tv, q.y, vacc[j].y);
            vacc[j].z = fmaf(tv, q.z, vacc[j].z);
            vacc[j].w = fmaf(tv, q.w, vacc[j].w);
        }
    }

    float* op = out + (size_t)dst * C_OUT;
#pragma unroll
    for (int j = 0; j < CO4; j++) {
        int co = 4 * j;
        if (co + 0 < C_OUT) atomicAdd(op + co + 0, vacc[j].x);
        if (co + 1 < C_OUT) atomicAdd(op + co + 1, vacc[j].y);
        if (co + 2 < C_OUT) atomicAdd(op + co + 2, vacc[j].z);
        if (co + 3 < C_OUT) atomicAdd(op + co + 3, vacc[j].w);
    }
}

// ---------------------------------------------------------------------------
// Host-side layer driver
// ---------------------------------------------------------------------------
template <int C_IN, int C_OUT>
static void run_layer(const float* xin,
                      const float* const* W,   // W1,b1,Wm1,bm1,Wm2,bm2,W2,b2
                      const void* edges, const float* ew,
                      float* A, float* B,
                      float* xout,
                      int N, int E, bool do_relu) {
    precomp_ab_kernel<C_IN><<<(N * NMSG + 255) / 256, 256>>>(xin, W[2], W[3], A, B, N);
    node_init_kernel<C_IN, C_OUT><<<(N * C_OUT + 255) / 256, 256>>>(xin, W[0], W[1], xout, N);
    edge_kernel<C_IN, C_OUT><<<(E + 255) / 256, 256>>>(
        edges, ew, xin, A, B, W[2], W[4], W[5], W[6], W[7], xout, E);
    if (do_relu)
        relu_kernel<<<(N * C_OUT + 255) / 256, 256>>>(xout, N * C_OUT);
}

extern "C" void kernel_launch(void* const* d_in, const int* in_sizes, int n_in,
                              void* d_out, int out_size) {
    const float* feat  = (const float*)d_in[0];
    const void*  edges = d_in[1];
    const float* ew    = (const float*)d_in[2];

    const float* P[24];
    for (int i = 0; i < 24; i++) P[i] = (const float*)d_in[3 + i];
    // P[0..7] = layer d, P[8..15] = layer h, P[16..23] = layer o

    int N = in_sizes[0];        // NUM_IN == 1, so element count == node count
    int E = in_sizes[2] / 2;    // weights is [E,2]

    float *x0, *x1, *A, *B;
    cudaGetSymbolAddress((void**)&x0, g_x0);
    cudaGetSymbolAddress((void**)&x1, g_x1);
    cudaGetSymbolAddress((void**)&A,  g_A);
    cudaGetSymbolAddress((void**)&B,  g_B);

    detect_edges_kernel<<<1, 32>>>((const long long*)edges);

    run_layer<1, 30>(feat, P + 0,  edges, ew, A, B, x0, N, E, true);   // layer d
    run_layer<30, 30>(x0,  P + 8,  edges, ew, A, B, x1, N, E, true);   // layer h (1)
    run_layer<30, 30>(x1,  P + 8,  edges, ew, A, B, x0, N, E, true);   // layer h (2)
    run_layer<30, 30>(x0,  P + 8,  edges, ew, A, B, x1, N, E, true);   // layer h (3)
    run_layer<30, 1>(x1,   P + 16, edges, ew, A, B, (float*)d_out, N, E, false); // layer o
}